// round 4
// baseline (speedup 1.0000x reference)
#include <cuda_runtime.h>
#include <math.h>

#define NN     128
#define PLANE  16384
#define STRIDE 129            // padded row stride (float2); 129 mod 16 == 1 -> conflict-free
#define BATCH  64
#define NJ     4
#define NL     4
#define NPAIR  6
#define NT     1024

#define C8 0.9238795325112867f
#define S8 0.3826834323650898f
#define RH 0.7071067811865476f

// ---------------- device scratch ----------------
static __device__ float2 g_ihat [BATCH * PLANE];                 // slot-k layout
static __device__ float2 g_u1hat[BATCH * NJ * NL * PLANE];       // slot-k layout
static __device__ float  g_psi  [NJ * NL * PLANE];               // slot-k layout
static __device__ float  g_s0   [BATCH];
static __device__ float  g_s1p  [BATCH * NJ * NL];
static __device__ float  g_s2p  [BATCH * NPAIR * NL * NL];

__device__ __constant__ int PJ1[NPAIR] = {0,0,0,1,1,2};
__device__ __constant__ int PJ2[NPAIR] = {1,2,3,2,3,3};

// ---------------- helpers ----------------
__device__ __forceinline__ float2 cmulf(float2 a, float2 b) {
    return make_float2(a.x*b.x - a.y*b.y, a.x*b.y + a.y*b.x);
}
__device__ __forceinline__ float2 caddf(float2 a, float2 b){ return make_float2(a.x+b.x, a.y+b.y); }
__device__ __forceinline__ float2 csubf(float2 a, float2 b){ return make_float2(a.x-b.x, a.y-b.y); }

__device__ __forceinline__ void init_tw(float2* tw, int tid) {
    if (tid < 128) {
        float s, c;
        __sincosf(-6.283185307179586f * (float)tid * (1.0f/128.0f), &s, &c);
        tw[tid] = make_float2(c, s);   // W_128^k
    }
}

__device__ __forceinline__ float fast_mag(float2 z) {
    float m2 = fmaf(z.x, z.x, z.y * z.y);
    float r;
    asm("sqrt.approx.f32 %0, %1;" : "=f"(r) : "f"(m2));
    return r;
}

// cheap W16 twiddle multiplies (forward = W^-... convention matches tw table: W = e^{-2pi i/16})
__device__ __forceinline__ float2 w1f(float2 v){ return make_float2(fmaf(C8,v.x, S8*v.y), fmaf(C8,v.y,-S8*v.x)); }
__device__ __forceinline__ float2 w2f(float2 v){ return make_float2(RH*(v.x+v.y), RH*(v.y-v.x)); }
__device__ __forceinline__ float2 w3f(float2 v){ return make_float2(fmaf(S8,v.x, C8*v.y), fmaf(S8,v.y,-C8*v.x)); }
__device__ __forceinline__ float2 w6f(float2 v){ return make_float2(RH*(v.y-v.x), -RH*(v.x+v.y)); }
__device__ __forceinline__ float2 mif(float2 v){ return make_float2(v.y, -v.x); }
__device__ __forceinline__ float2 w9f(float2 v){ float2 t=w1f(v); return make_float2(-t.x,-t.y); }
// conjugate versions (inverse)
__device__ __forceinline__ float2 w1c(float2 v){ return make_float2(fmaf(C8,v.x,-S8*v.y), fmaf(C8,v.y, S8*v.x)); }
__device__ __forceinline__ float2 w2c(float2 v){ return make_float2(RH*(v.x-v.y), RH*(v.x+v.y)); }
__device__ __forceinline__ float2 w3c(float2 v){ return make_float2(fmaf(S8,v.x,-C8*v.y), fmaf(S8,v.y, C8*v.x)); }
__device__ __forceinline__ float2 w6c(float2 v){ return make_float2(-RH*(v.x+v.y), RH*(v.x-v.y)); }
__device__ __forceinline__ float2 pic(float2 v){ return make_float2(-v.y, v.x); }
__device__ __forceinline__ float2 w9c(float2 v){ float2 t=w1c(v); return make_float2(-t.x,-t.y); }

// ---------------- 16-pt FFT, natural-in -> natural-k-out (forward) ----------------
__device__ __forceinline__ void fft16_fwd(float2 y[16]) {
    float2 z[16];
    {   // j=0
        float2 a=y[0],b=y[4],c=y[8],d=y[12];
        float2 t0=caddf(a,c), t1=csubf(a,c), t2=caddf(b,d), t3=csubf(b,d);
        z[0]=caddf(t0,t2);
        z[4]=make_float2(t1.x+t3.y, t1.y-t3.x);
        z[8]=csubf(t0,t2);
        z[12]=make_float2(t1.x-t3.y, t1.y+t3.x);
    }
    {   // j=1: twiddles W1, W2, W3
        float2 a=y[1],b=y[5],c=y[9],d=y[13];
        float2 t0=caddf(a,c), t1=csubf(a,c), t2=caddf(b,d), t3=csubf(b,d);
        z[1]=caddf(t0,t2);
        z[5]=w1f(make_float2(t1.x+t3.y, t1.y-t3.x));
        z[9]=w2f(csubf(t0,t2));
        z[13]=w3f(make_float2(t1.x-t3.y, t1.y+t3.x));
    }
    {   // j=2: W2, W4=-i, W6
        float2 a=y[2],b=y[6],c=y[10],d=y[14];
        float2 t0=caddf(a,c), t1=csubf(a,c), t2=caddf(b,d), t3=csubf(b,d);
        z[2]=caddf(t0,t2);
        z[6]=w2f(make_float2(t1.x+t3.y, t1.y-t3.x));
        z[10]=mif(csubf(t0,t2));
        z[14]=w6f(make_float2(t1.x-t3.y, t1.y+t3.x));
    }
    {   // j=3: W3, W6, W9
        float2 a=y[3],b=y[7],c=y[11],d=y[15];
        float2 t0=caddf(a,c), t1=csubf(a,c), t2=caddf(b,d), t3=csubf(b,d);
        z[3]=caddf(t0,t2);
        z[7]=w3f(make_float2(t1.x+t3.y, t1.y-t3.x));
        z[11]=w6f(csubf(t0,t2));
        z[15]=w9f(make_float2(t1.x-t3.y, t1.y+t3.x));
    }
    #pragma unroll
    for (int q = 0; q < 4; ++q) {   // stage B: X[4r+q] from z[4q..4q+3]
        float2 z0=z[4*q],z1=z[4*q+1],z2=z[4*q+2],z3=z[4*q+3];
        float2 s0=caddf(z0,z2), s1=csubf(z0,z2), s2=caddf(z1,z3), s3=csubf(z1,z3);
        y[q]    = caddf(s0,s2);
        y[4+q]  = make_float2(s1.x+s3.y, s1.y-s3.x);
        y[8+q]  = csubf(s0,s2);
        y[12+q] = make_float2(s1.x-s3.y, s1.y+s3.x);
    }
}

// 16-pt inverse (unnormalized), natural-k-in -> natural-n-out
__device__ __forceinline__ void fft16_inv(float2 y[16]) {
    float2 w[16];
    #pragma unroll
    for (int q = 0; q < 4; ++q) {
        float2 Y0=y[q], Y1=y[4+q], Y2=y[8+q], Y3=y[12+q];
        float2 u0=caddf(Y0,Y2), u1=csubf(Y0,Y2), u2=caddf(Y1,Y3), u3=csubf(Y1,Y3);
        w[4*q+0]=caddf(u0,u2);
        w[4*q+1]=make_float2(u1.x-u3.y, u1.y+u3.x);
        w[4*q+2]=csubf(u0,u2);
        w[4*q+3]=make_float2(u1.x+u3.y, u1.y-u3.x);
    }
    // conj twiddles (block q, element j -> W^{-jq})
    w[4+1]=w1c(w[4+1]);   w[4+2]=w2c(w[4+2]);   w[4+3]=w3c(w[4+3]);
    w[8+1]=w2c(w[8+1]);   w[8+2]=pic(w[8+2]);   w[8+3]=w6c(w[8+3]);
    w[12+1]=w3c(w[12+1]); w[12+2]=w6c(w[12+2]); w[12+3]=w9c(w[12+3]);
    #pragma unroll
    for (int j = 0; j < 4; ++j) {
        float2 w0=w[j], w1v=w[4+j], w2v=w[8+j], w3v=w[12+j];
        float2 v0=caddf(w0,w2v), v1=csubf(w0,w2v), v2=caddf(w1v,w3v), v3=csubf(w1v,w3v);
        y[j]    = caddf(v0,v2);
        y[j+4]  = make_float2(v1.x-v3.y, v1.y+v3.x);
        y[j+8]  = csubf(v0,v2);
        y[j+12] = make_float2(v1.x+v3.y, v1.y-v3.x);
    }
}

// ---------------- radix-8 part (stages m=64,32,16, W128 twiddles), per-thread 8 values stride 16
__device__ __forceinline__ void radix8_fwd(float2 x[8], int u, const float2* __restrict__ tw) {
    #pragma unroll
    for (int qi = 0; qi < 2; ++qi) {
        float2 a=x[qi], b=x[qi+2], c=x[qi+4], d=x[qi+6];
        float2 t3=caddf(a,c), t1=csubf(a,c);
        float2 t4=caddf(b,d), t2=csubf(b,d);
        int j = u + 16*qi;
        float2 w1=tw[j], w2=tw[2*j], w3=tw[3*j];
        x[qi]   = caddf(t3,t4);
        x[qi+2] = cmulf(csubf(t3,t4), w2);
        x[qi+4] = cmulf(make_float2(t1.x+t2.y, t1.y-t2.x), w1);
        x[qi+6] = cmulf(make_float2(t1.x-t2.y, t1.y+t2.x), w3);
    }
    float2 w = tw[u<<2];
    #pragma unroll
    for (int i = 0; i < 8; i += 2) {
        float2 a=x[i], b=x[i+1];
        x[i]   = caddf(a,b);
        x[i+1] = cmulf(csubf(a,b), w);
    }
}

__device__ __forceinline__ void radix8_inv(float2 x[8], int u, const float2* __restrict__ tw) {
    float2 w = tw[u<<2]; w.y = -w.y;
    #pragma unroll
    for (int i = 0; i < 8; i += 2) {
        float2 a=x[i], v=cmulf(x[i+1], w);
        x[i]=caddf(a,v); x[i+1]=csubf(a,v);
    }
    #pragma unroll
    for (int qi=0; qi<2; ++qi) {
        float2 a=x[qi], b=x[qi+2], c=x[qi+4], d=x[qi+6];
        int j = u+16*qi;
        float2 w1=tw[j], w2=tw[2*j], w3=tw[3*j];
        w1.y=-w1.y; w2.y=-w2.y; w3.y=-w3.y;
        float2 s1=cmulf(b,w2), s2=cmulf(c,w1), s3=cmulf(d,w3);
        float2 t3=caddf(a,s1), t4=csubf(a,s1);
        float2 t1=caddf(s2,s3);
        float2 t2=make_float2(s3.y-s2.y, s2.x-s3.x);
        x[qi]=caddf(t3,t1); x[qi+4]=csubf(t3,t1);
        x[qi+2]=caddf(t4,t2); x[qi+6]=csubf(t4,t2);
    }
}

// Deterministic block reduction; valid on tid==0. One __syncthreads inside.
__device__ __forceinline__ float block_sum(float v, float* red, int tid) {
    #pragma unroll
    for (int o = 16; o > 0; o >>= 1) v += __shfl_down_sync(0xffffffffu, v, o);
    if ((tid & 31) == 0) red[tid >> 5] = v;
    __syncthreads();
    float total = 0.0f;
    if (tid == 0) {
        #pragma unroll
        for (int w = 0; w < NT / 32; ++w) total += red[w];
    }
    return total;
}

// address -> frequency map for the slot-k layout: K(a) = (a&15)*8 + brev3(a>>4)
__device__ __forceinline__ int addr2freq(int a) {
    int i = a >> 4, k = a & 15;
    int b3 = ((i & 1) << 2) | (i & 2) | ((i >> 2) & 1);
    return k * 8 + b3;
}

// ---------------- kernel 1: Morlet bank in slot-k layout ----------------
__global__ void k_psi() {
    int idx = blockIdx.x * blockDim.x + threadIdx.x;
    if (idx >= NJ * NL * PLANE) return;
    int p   = idx >> 14;
    int pos = idx & (PLANE - 1);
    int r = addr2freq(pos >> 7);
    int c = addr2freq(pos & 127);
    int j = p >> 2, l = p & 3;
    float fr = (float)(r < 64 ? r : r - 128) * (6.283185307179586f / 128.0f);
    float fc = (float)(c < 64 ? c : c - 128) * (6.283185307179586f / 128.0f);
    float k0    = 2.356194490192345f / (float)(1 << j);
    float sigma = 0.8f * (float)(1 << j);
    float s2    = sigma * sigma;
    float theta = 0.7853981633974483f * (float)l;
    float k0x = k0 * cosf(theta), k0y = k0 * sinf(theta);
    float beta = expf(-0.5f * s2 * k0 * k0);
    float dx = fr - k0x, dy = fc - k0y;
    float g1 = expf(-0.5f * s2 * (dx*dx + dy*dy));
    float g0 = expf(-0.5f * s2 * (fr*fr + fc*fc));
    g_psi[idx] = g1 - beta * g0;
}

// ---------------- kernel 2: fft2(image) + s0 ----------------
__global__ void __launch_bounds__(NT, 1) k_img(const float* __restrict__ img) {
    extern __shared__ unsigned char smraw[];
    float2* S   = (float2*)smraw;
    float2* tw  = S + NN * STRIDE;
    float*  red = (float*)(tw + 128);
    int b = blockIdx.x, tid = threadIdx.x;
    int u = tid & 15, g = tid >> 4;
    init_tw(tw, tid);
    const float* ip = img + (size_t)b * PLANE;
    float lsum = 0.0f;
    for (int idx = tid; idx < PLANE; idx += NT) {
        float v = ip[idx];
        lsum += v;
        S[(idx >> 7) * STRIDE + (idx & 127)] = make_float2(v, 0.0f);
    }
    float tot = block_sum(lsum, red, tid);          // sync orders S + tw
    if (tid == 0) g_s0[b] = tot * (1.0f / 16384.0f);
    #pragma unroll
    for (int iter = 0; iter < 2; ++iter) {          // row radix-8 fwd
        int r = g + 64 * iter;
        float2 x[8];
        #pragma unroll
        for (int i = 0; i < 8; ++i) x[i] = S[r * STRIDE + u + 16*i];
        radix8_fwd(x, u, tw);
        #pragma unroll
        for (int i = 0; i < 8; ++i) S[r * STRIDE + u + 16*i] = x[i];
    }
    __syncthreads();
    {   // row 16-pt fwd
        int r = tid & 127, i = tid >> 7;
        int base = r * STRIDE + 16 * i;
        float2 y[16];
        #pragma unroll
        for (int m = 0; m < 16; ++m) y[m] = S[base + m];
        fft16_fwd(y);
        #pragma unroll
        for (int k = 0; k < 16; ++k) S[base + k] = y[k];
    }
    __syncthreads();
    #pragma unroll
    for (int iter = 0; iter < 2; ++iter) {          // col radix-8 fwd
        int c = g + 64 * iter;
        float2 x[8];
        #pragma unroll
        for (int i = 0; i < 8; ++i) x[i] = S[(u + 16*i) * STRIDE + c];
        radix8_fwd(x, u, tw);
        #pragma unroll
        for (int i = 0; i < 8; ++i) S[(u + 16*i) * STRIDE + c] = x[i];
    }
    __syncthreads();
    {   // col 16-pt fwd -> direct coalesced store
        int c = tid & 127, i = tid >> 7;
        float2 y[16];
        #pragma unroll
        for (int m = 0; m < 16; ++m) y[m] = S[(16*i + m) * STRIDE + c];
        fft16_fwd(y);
        float2* op = g_ihat + (size_t)b * PLANE;
        #pragma unroll
        for (int k = 0; k < 16; ++k) op[(16*i + k) * NN + c] = y[k];
    }
}

// ---------------- kernel 3: order 1 ----------------
__global__ void __launch_bounds__(NT, 1) k_o1() {
    extern __shared__ unsigned char smraw[];
    float2* S   = (float2*)smraw;
    float2* tw  = S + NN * STRIDE;
    float*  red = (float*)(tw + 128);
    int tid = threadIdx.x;
    int u = tid & 15, g = tid >> 4;
    int b  = blockIdx.x >> 4;
    int j1 = (blockIdx.x >> 2) & 3;
    int l1 = blockIdx.x & 3;
    init_tw(tw, tid);
    const float2* ih = g_ihat + (size_t)b * PLANE;
    const float*  ps = g_psi + (size_t)(j1 * NL + l1) * PLANE;
    for (int idx = tid; idx < PLANE; idx += NT) {
        float2 v = ih[idx];
        float  f = ps[idx];
        S[(idx >> 7) * STRIDE + (idx & 127)] = make_float2(v.x * f, v.y * f);
    }
    __syncthreads();
    {   // row 16-pt inv
        int r = tid & 127, i = tid >> 7;
        int base = r * STRIDE + 16 * i;
        float2 y[16];
        #pragma unroll
        for (int k = 0; k < 16; ++k) y[k] = S[base + k];
        fft16_inv(y);
        #pragma unroll
        for (int n = 0; n < 16; ++n) S[base + n] = y[n];
    }
    __syncthreads();
    #pragma unroll
    for (int iter = 0; iter < 2; ++iter) {          // row radix-8 inv
        int r = g + 64 * iter;
        float2 x[8];
        #pragma unroll
        for (int i = 0; i < 8; ++i) x[i] = S[r * STRIDE + u + 16*i];
        radix8_inv(x, u, tw);
        #pragma unroll
        for (int i = 0; i < 8; ++i) S[r * STRIDE + u + 16*i] = x[i];
    }
    __syncthreads();
    {   // col 16-pt inv
        int c = tid & 127, i = tid >> 7;
        float2 y[16];
        #pragma unroll
        for (int k = 0; k < 16; ++k) y[k] = S[(16*i + k) * STRIDE + c];
        fft16_inv(y);
        #pragma unroll
        for (int n = 0; n < 16; ++n) S[(16*i + n) * STRIDE + c] = y[n];
    }
    __syncthreads();
    float lsum = 0.0f;
    #pragma unroll
    for (int iter = 0; iter < 2; ++iter) {          // col radix-8 inv + |.| + col radix-8 fwd (fused)
        int c = g + 64 * iter;
        float2 x[8];
        #pragma unroll
        for (int i = 0; i < 8; ++i) x[i] = S[(u + 16*i) * STRIDE + c];
        radix8_inv(x, u, tw);
        #pragma unroll
        for (int i = 0; i < 8; ++i) {
            float m = fast_mag(x[i]) * (1.0f / 16384.0f);
            lsum += m;
            x[i] = make_float2(m, 0.0f);
        }
        radix8_fwd(x, u, tw);
        #pragma unroll
        for (int i = 0; i < 8; ++i) S[(u + 16*i) * STRIDE + c] = x[i];
    }
    float tot = block_sum(lsum, red, tid);          // sync orders S stores
    if (tid == 0) g_s1p[blockIdx.x] = tot;
    {   // col 16-pt fwd
        int c = tid & 127, i = tid >> 7;
        float2 y[16];
        #pragma unroll
        for (int m = 0; m < 16; ++m) y[m] = S[(16*i + m) * STRIDE + c];
        fft16_fwd(y);
        #pragma unroll
        for (int k = 0; k < 16; ++k) S[(16*i + k) * STRIDE + c] = y[k];
    }
    __syncthreads();
    #pragma unroll
    for (int iter = 0; iter < 2; ++iter) {          // row radix-8 fwd
        int r = g + 64 * iter;
        float2 x[8];
        #pragma unroll
        for (int i = 0; i < 8; ++i) x[i] = S[r * STRIDE + u + 16*i];
        radix8_fwd(x, u, tw);
        #pragma unroll
        for (int i = 0; i < 8; ++i) S[r * STRIDE + u + 16*i] = x[i];
    }
    __syncthreads();
    {   // row 16-pt fwd, store into S
        int r = tid & 127, i = tid >> 7;
        int base = r * STRIDE + 16 * i;
        float2 y[16];
        #pragma unroll
        for (int m = 0; m < 16; ++m) y[m] = S[base + m];
        fft16_fwd(y);
        #pragma unroll
        for (int k = 0; k < 16; ++k) S[base + k] = y[k];
    }
    __syncthreads();
    // coalesced copy out
    float2* op = g_u1hat + (size_t)blockIdx.x * PLANE;
    for (int idx = tid; idx < PLANE; idx += NT)
        op[idx] = S[(idx >> 7) * STRIDE + (idx & 127)];
}

// ---------------- kernel 4: order 2 ----------------
__global__ void __launch_bounds__(NT, 1) k_o2() {
    extern __shared__ unsigned char smraw[];
    float2* S   = (float2*)smraw;
    float2* tw  = S + NN * STRIDE;
    float*  red = (float*)(tw + 128);
    int tid = threadIdx.x;
    int u = tid & 15, g = tid >> 4;
    int b    = blockIdx.x / 96;
    int rem  = blockIdx.x - b * 96;
    int pair = rem >> 4;
    int l1   = (rem >> 2) & 3;
    int l2   = rem & 3;
    int j1 = PJ1[pair], j2 = PJ2[pair];
    init_tw(tw, tid);
    const float2* uh = g_u1hat + (size_t)(((b * NJ + j1) * NL) + l1) * PLANE;
    const float*  ps = g_psi + (size_t)(j2 * NL + l2) * PLANE;
    for (int idx = tid; idx < PLANE; idx += NT) {
        float2 v = uh[idx];
        float  f = ps[idx];
        S[(idx >> 7) * STRIDE + (idx & 127)] = make_float2(v.x * f, v.y * f);
    }
    __syncthreads();
    {   // row 16-pt inv
        int r = tid & 127, i = tid >> 7;
        int base = r * STRIDE + 16 * i;
        float2 y[16];
        #pragma unroll
        for (int k = 0; k < 16; ++k) y[k] = S[base + k];
        fft16_inv(y);
        #pragma unroll
        for (int n = 0; n < 16; ++n) S[base + n] = y[n];
    }
    __syncthreads();
    #pragma unroll
    for (int iter = 0; iter < 2; ++iter) {          // row radix-8 inv
        int r = g + 64 * iter;
        float2 x[8];
        #pragma unroll
        for (int i = 0; i < 8; ++i) x[i] = S[r * STRIDE + u + 16*i];
        radix8_inv(x, u, tw);
        #pragma unroll
        for (int i = 0; i < 8; ++i) S[r * STRIDE + u + 16*i] = x[i];
    }
    __syncthreads();
    {   // col 16-pt inv
        int c = tid & 127, i = tid >> 7;
        float2 y[16];
        #pragma unroll
        for (int k = 0; k < 16; ++k) y[k] = S[(16*i + k) * STRIDE + c];
        fft16_inv(y);
        #pragma unroll
        for (int n = 0; n < 16; ++n) S[(16*i + n) * STRIDE + c] = y[n];
    }
    __syncthreads();
    float lsum = 0.0f;
    #pragma unroll
    for (int iter = 0; iter < 2; ++iter) {          // col radix-8 inv, |.| from regs
        int c = g + 64 * iter;
        float2 x[8];
        #pragma unroll
        for (int i = 0; i < 8; ++i) x[i] = S[(u + 16*i) * STRIDE + c];
        radix8_inv(x, u, tw);
        #pragma unroll
        for (int i = 0; i < 8; ++i) lsum += fast_mag(x[i]);
    }
    float tot = block_sum(lsum, red, tid);
    if (tid == 0) g_s2p[blockIdx.x] = tot;
}

// ---------------- kernel 5: combine + MLP ----------------
__global__ void k_head(const float* __restrict__ fc1w, const float* __restrict__ fc1b,
                       const float* __restrict__ fc2w, const float* __restrict__ fc2b,
                       float* __restrict__ out) {
    int b = blockIdx.x;
    if (threadIdx.x != 0) return;
    float coeff[11];
    coeff[0] = g_s0[b];
    #pragma unroll
    for (int j = 0; j < 4; ++j) {
        float s = 0.0f;
        #pragma unroll
        for (int l = 0; l < 4; ++l) s += g_s1p[(b * 4 + j) * 4 + l];
        coeff[1 + j] = s * (1.0f / (4.0f * 16384.0f));
    }
    #pragma unroll
    for (int p = 0; p < 6; ++p) {
        float s = 0.0f;
        #pragma unroll
        for (int k = 0; k < 16; ++k) s += g_s2p[(b * 6 + p) * 16 + k];
        coeff[5 + p] = s * (1.0f / 16384.0f) * (1.0f / (16.0f * 16384.0f));
    }
    float h[4];
    #pragma unroll
    for (int k = 0; k < 4; ++k) {
        float a = fc1b[k];
        #pragma unroll
        for (int i = 0; i < 11; ++i) a += coeff[i] * fc1w[k * 11 + i];
        h[k] = fmaxf(a, 0.0f);
    }
    #pragma unroll
    for (int o = 0; o < 10; ++o) {
        float a = fc2b[o];
        #pragma unroll
        for (int k = 0; k < 4; ++k) a += h[k] * fc2w[o * 4 + k];
        out[b * 10 + o] = 1.0f / (1.0f + expf(-a));
    }
}

// ---------------- launch ----------------
extern "C" void kernel_launch(void* const* d_in, const int* in_sizes, int n_in,
                              void* d_out, int out_size) {
    (void)in_sizes; (void)n_in; (void)out_size;
    const float* img  = (const float*)d_in[0];
    const float* fc1w = (const float*)d_in[1];
    const float* fc1b = (const float*)d_in[2];
    const float* fc2w = (const float*)d_in[3];
    const float* fc2b = (const float*)d_in[4];
    float* out = (float*)d_out;

    const size_t SMEM_SZ = (size_t)(NN * STRIDE + 128) * sizeof(float2) + (NT / 32) * sizeof(float);
    cudaFuncSetAttribute(k_img, cudaFuncAttributeMaxDynamicSharedMemorySize, (int)SMEM_SZ);
    cudaFuncSetAttribute(k_o1,  cudaFuncAttributeMaxDynamicSharedMemorySize, (int)SMEM_SZ);
    cudaFuncSetAttribute(k_o2,  cudaFuncAttributeMaxDynamicSharedMemorySize, (int)SMEM_SZ);

    k_psi<<<(NJ * NL * PLANE + 255) / 256, 256>>>();
    k_img<<<BATCH, NT, SMEM_SZ>>>(img);
    k_o1 <<<BATCH * NJ * NL, NT, SMEM_SZ>>>();
    k_o2 <<<BATCH * NPAIR * NL * NL, NT, SMEM_SZ>>>();
    k_head<<<BATCH, 32>>>(fc1w, fc1b, fc2w, fc2b, out);
}

// round 6
// speedup vs baseline: 1.1888x; 1.1888x over previous
#include <cuda_runtime.h>
#include <math.h>

#define NN     128
#define PLANE  16384
#define STRIDE 129            // padded row stride (float2)
#define BATCH  64
#define NJ     4
#define NL     4
#define NPAIR  6
#define NT     1024           // threads per FFT block (32 warps)

// ---------------- device scratch ----------------
static __device__ float2 g_ihat [BATCH * PLANE];                 // bitrev order
static __device__ float2 g_u1hat[BATCH * NJ * NL * PLANE];       // bitrev order
static __device__ float  g_psi  [NJ * NL * PLANE];               // bitrev order
static __device__ float  g_s0   [BATCH];
static __device__ float  g_s1p  [BATCH * NJ * NL];
static __device__ float  g_s2p  [BATCH * NPAIR * NL * NL];

__device__ __constant__ int PJ1[NPAIR] = {0,0,0,1,1,2};
__device__ __constant__ int PJ2[NPAIR] = {1,2,3,2,3,3};

// ---------------- helpers ----------------
__device__ __forceinline__ float2 cmulf(float2 a, float2 b) {
    return make_float2(a.x*b.x - a.y*b.y, a.x*b.y + a.y*b.x);
}
__device__ __forceinline__ float2 caddf(float2 a, float2 b){ return make_float2(a.x+b.x, a.y+b.y); }
__device__ __forceinline__ float2 csubf(float2 a, float2 b){ return make_float2(a.x-b.x, a.y-b.y); }

__device__ __forceinline__ void init_tw(float2* tw, int tid) {
    if (tid < 128) {
        float s, c;
        __sincosf(-6.283185307179586f * (float)tid * (1.0f/128.0f), &s, &c);
        tw[tid] = make_float2(c, s);   // W_128^k
    }
}

__device__ __forceinline__ float2 shflx(float2 v, int h) {
    float2 o;
    o.x = __shfl_xor_sync(0xffffffffu, v.x, h);
    o.y = __shfl_xor_sync(0xffffffffu, v.y, h);
    return o;
}

__device__ __forceinline__ float fast_mag(float2 z) {
    float m2 = fmaf(z.x, z.x, z.y * z.y);
    float r;
    asm("sqrt.approx.f32 %0, %1;" : "=f"(r) : "f"(m2));
    return r;
}

// ---------------- 128-pt FFT: 16 lanes x 8 regs, position p = u + 16*i ----------------
// Forward DIF: natural in -> bit-reversed out.
__device__ __forceinline__ void fft128_fwd(float2 x[8], int u, const float2* __restrict__ tw) {
    // merged radix-4 (stages m=64,32) on quartets (qi, qi+2, qi+4, qi+6)
    #pragma unroll
    for (int qi = 0; qi < 2; ++qi) {
        float2 a = x[qi], b = x[qi+2], c = x[qi+4], d = x[qi+6];
        float2 t3 = caddf(a, c), t1 = csubf(a, c);
        float2 t4 = caddf(b, d), t2 = csubf(b, d);
        int j = u + 16 * qi;
        float2 w1 = tw[j], w2 = tw[2*j], w3 = tw[3*j];
        x[qi]   = caddf(t3, t4);
        x[qi+2] = cmulf(csubf(t3, t4), w2);
        x[qi+4] = cmulf(make_float2(t1.x + t2.y, t1.y - t2.x), w1);  // (t1 - i t2) W^j
        x[qi+6] = cmulf(make_float2(t1.x - t2.y, t1.y + t2.x), w3);  // (t1 + i t2) W^3j
    }
    // stage m=16: pairs (i, i+1), same twiddle all pairs
    {
        float2 w = tw[u << 2];
        #pragma unroll
        for (int i = 0; i < 8; i += 2) {
            float2 a = x[i], b = x[i+1];
            x[i]   = caddf(a, b);
            x[i+1] = cmulf(csubf(a, b), w);
        }
    }
    // shuffle stages h = 8,4,2,1 — select-free
    #pragma unroll
    for (int s = 3; s < 7; ++s) {
        int h = 64 >> s;
        bool lower = (u & h) == 0;
        float sgn = lower ? 1.0f : -1.0f;
        float2 wst = tw[(u & (h - 1)) << s];
        float2 we  = lower ? make_float2(1.0f, 0.0f) : wst;
        #pragma unroll
        for (int i = 0; i < 8; ++i) {
            float2 v = x[i];
            float2 o = shflx(v, h);
            float2 t = make_float2(fmaf(sgn, v.x, o.x), fmaf(sgn, v.y, o.y));
            x[i] = cmulf(t, we);
        }
    }
}

// Inverse DIT (unnormalized, x16384 total): bit-reversed in -> natural out.
__device__ __forceinline__ void fft128_inv(float2 x[8], int u, const float2* __restrict__ tw) {
    // shuffle stages h = 1,2,4,8 — select-free
    #pragma unroll
    for (int s = 6; s >= 3; --s) {
        int h = 64 >> s;
        bool lower = (u & h) == 0;
        float sgn = lower ? 1.0f : -1.0f;
        float2 wst = tw[(u & (h - 1)) << s];
        float2 we  = lower ? make_float2(1.0f, 0.0f) : make_float2(wst.x, -wst.y);
        #pragma unroll
        for (int i = 0; i < 8; ++i) {
            float2 t = cmulf(x[i], we);
            float2 o = shflx(t, h);
            x[i] = make_float2(fmaf(sgn, t.x, o.x), fmaf(sgn, t.y, o.y));
        }
    }
    // stage m=16 inverse
    {
        float2 w = tw[u << 2]; w.y = -w.y;
        #pragma unroll
        for (int i = 0; i < 8; i += 2) {
            float2 a = x[i], v = cmulf(x[i+1], w);
            x[i]   = caddf(a, v);
            x[i+1] = csubf(a, v);
        }
    }
    // merged inverse radix-4 (stages m=32,64): 3 cmuls per quartet
    #pragma unroll
    for (int qi = 0; qi < 2; ++qi) {
        float2 a = x[qi], b = x[qi+2], c = x[qi+4], d = x[qi+6];
        int j = u + 16 * qi;
        float2 w1 = tw[j],   w2 = tw[2*j],   w3 = tw[3*j];
        w1.y = -w1.y; w2.y = -w2.y; w3.y = -w3.y;
        float2 s1 = cmulf(b, w2);
        float2 s2 = cmulf(c, w1);
        float2 s3 = cmulf(d, w3);
        float2 t3 = caddf(a, s1);
        float2 t4 = csubf(a, s1);
        float2 t1 = caddf(s2, s3);
        float2 t2 = make_float2(s3.y - s2.y, s2.x - s3.x);
        x[qi]   = caddf(t3, t1);
        x[qi+4] = csubf(t3, t1);
        x[qi+2] = caddf(t4, t2);
        x[qi+6] = csubf(t4, t2);
    }
}

// Deterministic block reduction; valid on tid==0. One __syncthreads inside.
__device__ __forceinline__ float block_sum(float v, float* red, int tid) {
    #pragma unroll
    for (int o = 16; o > 0; o >>= 1) v += __shfl_down_sync(0xffffffffu, v, o);
    if ((tid & 31) == 0) red[tid >> 5] = v;
    __syncthreads();
    float total = 0.0f;
    if (tid == 0) {
        #pragma unroll
        for (int w = 0; w < NT / 32; ++w) total += red[w];
    }
    return total;
}

// ---------------- kernel 1: Morlet bank, pre-permuted to 2D-bitrev ----------------
__global__ void k_psi() {
    int idx = blockIdx.x * blockDim.x + threadIdx.x;
    if (idx >= NJ * NL * PLANE) return;
    int p   = idx >> 14;
    int pos = idx & (PLANE - 1);
    int R = pos >> 7, C = pos & 127;
    int r = __brev((unsigned)R) >> 25;
    int c = __brev((unsigned)C) >> 25;
    int j = p >> 2, l = p & 3;
    float fr = (float)(r < 64 ? r : r - 128) * (6.283185307179586f / 128.0f);
    float fc = (float)(c < 64 ? c : c - 128) * (6.283185307179586f / 128.0f);
    float k0    = 2.356194490192345f / (float)(1 << j);
    float sigma = 0.8f * (float)(1 << j);
    float s2    = sigma * sigma;
    float theta = 0.7853981633974483f * (float)l;
    float k0x = k0 * cosf(theta), k0y = k0 * sinf(theta);
    float beta = expf(-0.5f * s2 * k0 * k0);
    float dx = fr - k0x, dy = fc - k0y;
    float g1 = expf(-0.5f * s2 * (dx*dx + dy*dy));
    float g0 = expf(-0.5f * s2 * (fr*fr + fc*fc));
    g_psi[idx] = g1 - beta * g0;
}

// ---------------- kernel 2: fft2(image) + s0 (fused gmem load into row pass) ----------------
__global__ void __launch_bounds__(NT, 1) k_img(const float* __restrict__ img) {
    extern __shared__ unsigned char smraw[];
    float2* S   = (float2*)smraw;
    float2* tw  = S + NN * STRIDE;
    float*  red = (float*)(tw + 128);
    int b = blockIdx.x, tid = threadIdx.x;
    int u = tid & 15, g = tid >> 4;
    init_tw(tw, tid);
    __syncthreads();                                // tw visible
    const float* ip = img + (size_t)b * PLANE;
    float lsum = 0.0f;
    #pragma unroll
    for (int iter = 0; iter < 2; ++iter) {          // fused load + row forward
        int r = g + 64 * iter;
        float2 x[8];
        #pragma unroll
        for (int i = 0; i < 8; ++i) {
            float v = ip[r * NN + u + 16*i];
            lsum += v;
            x[i] = make_float2(v, 0.0f);
        }
        fft128_fwd(x, u, tw);
        #pragma unroll
        for (int i = 0; i < 8; ++i) S[r * STRIDE + u + 16*i] = x[i];
    }
    float tot = block_sum(lsum, red, tid);          // sync inside orders S stores
    if (tid == 0) g_s0[b] = tot * (1.0f / 16384.0f);
    #pragma unroll
    for (int iter = 0; iter < 2; ++iter) {          // column forward
        int c = g + 64 * iter;
        float2 x[8];
        #pragma unroll
        for (int i = 0; i < 8; ++i) x[i] = S[(u + 16*i) * STRIDE + c];
        fft128_fwd(x, u, tw);
        #pragma unroll
        for (int i = 0; i < 8; ++i) S[(u + 16*i) * STRIDE + c] = x[i];
    }
    __syncthreads();
    float2* op = g_ihat + (size_t)b * PLANE;
    for (int i = tid; i < PLANE; i += NT)
        op[i] = S[(i >> 7) * STRIDE + (i & 127)];
}

// ---------------- kernel 3: order 1 (fused load*psi into inverse-row pass) ----------------
__global__ void __launch_bounds__(NT, 1) k_o1() {
    extern __shared__ unsigned char smraw[];
    float2* S   = (float2*)smraw;
    float2* tw  = S + NN * STRIDE;
    float*  red = (float*)(tw + 128);
    int tid = threadIdx.x;
    int u = tid & 15, g = tid >> 4;
    int b  = blockIdx.x >> 4;
    int j1 = (blockIdx.x >> 2) & 3;
    int l1 = blockIdx.x & 3;
    init_tw(tw, tid);
    __syncthreads();                                // tw visible
    const float2* ih = g_ihat + (size_t)b * PLANE;
    const float*  ps = g_psi + (size_t)(j1 * NL + l1) * PLANE;
    #pragma unroll
    for (int iter = 0; iter < 2; ++iter) {          // fused load*psi + inverse rows
        int r = g + 64 * iter;
        float2 x[8];
        #pragma unroll
        for (int i = 0; i < 8; ++i) {
            int p = r * NN + u + 16*i;
            float2 v = ih[p];
            float  f = ps[p];
            x[i] = make_float2(v.x * f, v.y * f);
        }
        fft128_inv(x, u, tw);
        #pragma unroll
        for (int i = 0; i < 8; ++i) S[r * STRIDE + u + 16*i] = x[i];
    }
    __syncthreads();
    float lsum = 0.0f;
    #pragma unroll
    for (int iter = 0; iter < 2; ++iter) {          // inverse cols -> |.| -> forward cols
        int c = g + 64 * iter;
        float2 x[8];
        #pragma unroll
        for (int i = 0; i < 8; ++i) x[i] = S[(u + 16*i) * STRIDE + c];
        fft128_inv(x, u, tw);
        #pragma unroll
        for (int i = 0; i < 8; ++i) {
            float m = fast_mag(x[i]) * (1.0f / 16384.0f);
            lsum += m;
            x[i] = make_float2(m, 0.0f);
        }
        fft128_fwd(x, u, tw);
        #pragma unroll
        for (int i = 0; i < 8; ++i) S[(u + 16*i) * STRIDE + c] = x[i];
    }
    float tot = block_sum(lsum, red, tid);          // sync inside orders S stores
    if (tid == 0) g_s1p[blockIdx.x] = tot;
    float2* op = g_u1hat + (size_t)blockIdx.x * PLANE;
    #pragma unroll
    for (int iter = 0; iter < 2; ++iter) {          // forward rows, write out from regs
        int r = g + 64 * iter;
        float2 x[8];
        #pragma unroll
        for (int i = 0; i < 8; ++i) x[i] = S[r * STRIDE + u + 16*i];
        fft128_fwd(x, u, tw);
        #pragma unroll
        for (int i = 0; i < 8; ++i) op[r * NN + u + 16*i] = x[i];
    }
}

// ---------------- kernel 4: order 2 (fused load*psi into inverse-row pass) ----------------
__global__ void __launch_bounds__(NT, 1) k_o2() {
    extern __shared__ unsigned char smraw[];
    float2* S   = (float2*)smraw;
    float2* tw  = S + NN * STRIDE;
    float*  red = (float*)(tw + 128);
    int tid = threadIdx.x;
    int u = tid & 15, g = tid >> 4;
    int b    = blockIdx.x / 96;
    int rem  = blockIdx.x - b * 96;
    int pair = rem >> 4;
    int l1   = (rem >> 2) & 3;
    int l2   = rem & 3;
    int j1 = PJ1[pair], j2 = PJ2[pair];
    init_tw(tw, tid);
    __syncthreads();                                // tw visible
    const float2* uh = g_u1hat + (size_t)(((b * NJ + j1) * NL) + l1) * PLANE;
    const float*  ps = g_psi + (size_t)(j2 * NL + l2) * PLANE;
    #pragma unroll
    for (int iter = 0; iter < 2; ++iter) {          // fused load*psi + inverse rows
        int r = g + 64 * iter;
        float2 x[8];
        #pragma unroll
        for (int i = 0; i < 8; ++i) {
            int p = r * NN + u + 16*i;
            float2 v = uh[p];
            float  f = ps[p];
            x[i] = make_float2(v.x * f, v.y * f);
        }
        fft128_inv(x, u, tw);
        #pragma unroll
        for (int i = 0; i < 8; ++i) S[r * STRIDE + u + 16*i] = x[i];
    }
    __syncthreads();
    float lsum = 0.0f;
    #pragma unroll
    for (int iter = 0; iter < 2; ++iter) {          // inverse cols, |.| from regs
        int c = g + 64 * iter;
        float2 x[8];
        #pragma unroll
        for (int i = 0; i < 8; ++i) x[i] = S[(u + 16*i) * STRIDE + c];
        fft128_inv(x, u, tw);
        #pragma unroll
        for (int i = 0; i < 8; ++i)
            lsum += fast_mag(x[i]);
    }
    float tot = block_sum(lsum, red, tid);
    if (tid == 0) g_s2p[blockIdx.x] = tot;
}

// ---------------- kernel 5: combine + MLP ----------------
__global__ void k_head(const float* __restrict__ fc1w, const float* __restrict__ fc1b,
                       const float* __restrict__ fc2w, const float* __restrict__ fc2b,
                       float* __restrict__ out) {
    int b = blockIdx.x;
    if (threadIdx.x != 0) return;
    float coeff[11];
    coeff[0] = g_s0[b];
    #pragma unroll
    for (int j = 0; j < 4; ++j) {
        float s = 0.0f;
        #pragma unroll
        for (int l = 0; l < 4; ++l) s += g_s1p[(b * 4 + j) * 4 + l];
        coeff[1 + j] = s * (1.0f / (4.0f * 16384.0f));
    }
    #pragma unroll
    for (int p = 0; p < 6; ++p) {
        float s = 0.0f;
        #pragma unroll
        for (int k = 0; k < 16; ++k) s += g_s2p[(b * 6 + p) * 16 + k];
        coeff[5 + p] = s * (1.0f / 16384.0f) * (1.0f / (16.0f * 16384.0f));
    }
    float h[4];
    #pragma unroll
    for (int k = 0; k < 4; ++k) {
        float a = fc1b[k];
        #pragma unroll
        for (int i = 0; i < 11; ++i) a += coeff[i] * fc1w[k * 11 + i];
        h[k] = fmaxf(a, 0.0f);
    }
    #pragma unroll
    for (int o = 0; o < 10; ++o) {
        float a = fc2b[o];
        #pragma unroll
        for (int k = 0; k < 4; ++k) a += h[k] * fc2w[o * 4 + k];
        out[b * 10 + o] = 1.0f / (1.0f + expf(-a));
    }
}

// ---------------- launch ----------------
extern "C" void kernel_launch(void* const* d_in, const int* in_sizes, int n_in,
                              void* d_out, int out_size) {
    (void)in_sizes; (void)n_in; (void)out_size;
    const float* img  = (const float*)d_in[0];
    const float* fc1w = (const float*)d_in[1];
    const float* fc1b = (const float*)d_in[2];
    const float* fc2w = (const float*)d_in[3];
    const float* fc2b = (const float*)d_in[4];
    float* out = (float*)d_out;

    const size_t SMEM_SZ = (size_t)(NN * STRIDE + 128) * sizeof(float2) + (NT / 32) * sizeof(float);
    cudaFuncSetAttribute(k_img, cudaFuncAttributeMaxDynamicSharedMemorySize, (int)SMEM_SZ);
    cudaFuncSetAttribute(k_o1,  cudaFuncAttributeMaxDynamicSharedMemorySize, (int)SMEM_SZ);
    cudaFuncSetAttribute(k_o2,  cudaFuncAttributeMaxDynamicSharedMemorySize, (int)SMEM_SZ);

    k_psi<<<(NJ * NL * PLANE + 255) / 256, 256>>>();
    k_img<<<BATCH, NT, SMEM_SZ>>>(img);
    k_o1 <<<BATCH * NJ * NL, NT, SMEM_SZ>>>();
    k_o2 <<<BATCH * NPAIR * NL * NL, NT, SMEM_SZ>>>();
    k_head<<<BATCH, 32>>>(fc1w, fc1b, fc2w, fc2b, out);
}

// round 7
// speedup vs baseline: 1.3138x; 1.1051x over previous
#include <cuda_runtime.h>
#include <cuda_fp16.h>
#include <math.h>

#define NN     128
#define PLANE  16384
#define STRIDE 129            // fp32 plane stride (k_img)
#define STRH   130            // half2 plane stride (k_o1/k_o2), conflict-free maps
#define BATCH  64
#define NJ     4
#define NL     4
#define NPAIR  6
#define NTI    1024           // k_img threads
#define NTS    512            // k_o1/k_o2 threads (2 CTAs/SM)

#define SH_PLANE_BYTES (NN * STRH * sizeof(__half2))   // 66560

// ---------------- device scratch ----------------
static __device__ float2 g_ihat [BATCH * PLANE];                 // bitrev order
static __device__ float2 g_u1hat[BATCH * NJ * NL * PLANE];       // bitrev order
static __device__ float  g_psi  [NJ * NL * PLANE];               // bitrev order
static __device__ float  g_s0   [BATCH];
static __device__ float  g_s1p  [BATCH * NJ * NL];
static __device__ float  g_s2p  [BATCH * NPAIR * NL * NL];

__device__ __constant__ int PJ1[NPAIR] = {0,0,0,1,1,2};
__device__ __constant__ int PJ2[NPAIR] = {1,2,3,2,3,3};

// ---------------- helpers ----------------
__device__ __forceinline__ float2 cmulf(float2 a, float2 b) {
    return make_float2(a.x*b.x - a.y*b.y, a.x*b.y + a.y*b.x);
}
__device__ __forceinline__ float2 caddf(float2 a, float2 b){ return make_float2(a.x+b.x, a.y+b.y); }
__device__ __forceinline__ float2 csubf(float2 a, float2 b){ return make_float2(a.x-b.x, a.y-b.y); }

__device__ __forceinline__ void init_tw(float2* tw, int tid) {
    if (tid < 128) {
        float s, c;
        __sincosf(-6.283185307179586f * (float)tid * (1.0f/128.0f), &s, &c);
        tw[tid] = make_float2(c, s);   // W_128^k
    }
}

__device__ __forceinline__ float2 shflx(float2 v, int h) {
    float2 o;
    o.x = __shfl_xor_sync(0xffffffffu, v.x, h);
    o.y = __shfl_xor_sync(0xffffffffu, v.y, h);
    return o;
}

__device__ __forceinline__ float fast_mag(float2 z) {
    float m2 = fmaf(z.x, z.x, z.y * z.y);
    float r;
    asm("sqrt.approx.f32 %0, %1;" : "=f"(r) : "f"(m2));
    return r;
}

// ---------------- 128-pt FFT: 16 lanes x 8 regs, position p = u + 16*i ----------------
// Forward DIF: natural in -> bit-reversed out.
__device__ __forceinline__ void fft128_fwd(float2 x[8], int u, const float2* __restrict__ tw) {
    #pragma unroll
    for (int qi = 0; qi < 2; ++qi) {
        float2 a = x[qi], b = x[qi+2], c = x[qi+4], d = x[qi+6];
        float2 t3 = caddf(a, c), t1 = csubf(a, c);
        float2 t4 = caddf(b, d), t2 = csubf(b, d);
        int j = u + 16 * qi;
        float2 w1 = tw[j], w2 = tw[2*j], w3 = tw[3*j];
        x[qi]   = caddf(t3, t4);
        x[qi+2] = cmulf(csubf(t3, t4), w2);
        x[qi+4] = cmulf(make_float2(t1.x + t2.y, t1.y - t2.x), w1);
        x[qi+6] = cmulf(make_float2(t1.x - t2.y, t1.y + t2.x), w3);
    }
    {
        float2 w = tw[u << 2];
        #pragma unroll
        for (int i = 0; i < 8; i += 2) {
            float2 a = x[i], b = x[i+1];
            x[i]   = caddf(a, b);
            x[i+1] = cmulf(csubf(a, b), w);
        }
    }
    #pragma unroll
    for (int s = 3; s < 7; ++s) {
        int h = 64 >> s;
        bool lower = (u & h) == 0;
        float sgn = lower ? 1.0f : -1.0f;
        float2 wst = tw[(u & (h - 1)) << s];
        float2 we  = lower ? make_float2(1.0f, 0.0f) : wst;
        #pragma unroll
        for (int i = 0; i < 8; ++i) {
            float2 v = x[i];
            float2 o = shflx(v, h);
            float2 t = make_float2(fmaf(sgn, v.x, o.x), fmaf(sgn, v.y, o.y));
            x[i] = cmulf(t, we);
        }
    }
}

// Inverse DIT (unnormalized): bit-reversed in -> natural out.
__device__ __forceinline__ void fft128_inv(float2 x[8], int u, const float2* __restrict__ tw) {
    #pragma unroll
    for (int s = 6; s >= 3; --s) {
        int h = 64 >> s;
        bool lower = (u & h) == 0;
        float sgn = lower ? 1.0f : -1.0f;
        float2 wst = tw[(u & (h - 1)) << s];
        float2 we  = lower ? make_float2(1.0f, 0.0f) : make_float2(wst.x, -wst.y);
        #pragma unroll
        for (int i = 0; i < 8; ++i) {
            float2 t = cmulf(x[i], we);
            float2 o = shflx(t, h);
            x[i] = make_float2(fmaf(sgn, t.x, o.x), fmaf(sgn, t.y, o.y));
        }
    }
    {
        float2 w = tw[u << 2]; w.y = -w.y;
        #pragma unroll
        for (int i = 0; i < 8; i += 2) {
            float2 a = x[i], v = cmulf(x[i+1], w);
            x[i]   = caddf(a, v);
            x[i+1] = csubf(a, v);
        }
    }
    #pragma unroll
    for (int qi = 0; qi < 2; ++qi) {
        float2 a = x[qi], b = x[qi+2], c = x[qi+4], d = x[qi+6];
        int j = u + 16 * qi;
        float2 w1 = tw[j],   w2 = tw[2*j],   w3 = tw[3*j];
        w1.y = -w1.y; w2.y = -w2.y; w3.y = -w3.y;
        float2 s1 = cmulf(b, w2);
        float2 s2 = cmulf(c, w1);
        float2 s3 = cmulf(d, w3);
        float2 t3 = caddf(a, s1);
        float2 t4 = csubf(a, s1);
        float2 t1 = caddf(s2, s3);
        float2 t2 = make_float2(s3.y - s2.y, s2.x - s3.x);
        x[qi]   = caddf(t3, t1);
        x[qi+4] = csubf(t3, t1);
        x[qi+2] = caddf(t4, t2);
        x[qi+6] = csubf(t4, t2);
    }
}

// Deterministic block reduction; valid on tid==0. One __syncthreads inside.
template<int NWARPS>
__device__ __forceinline__ float block_sum(float v, float* red, int tid) {
    #pragma unroll
    for (int o = 16; o > 0; o >>= 1) v += __shfl_down_sync(0xffffffffu, v, o);
    if ((tid & 31) == 0) red[tid >> 5] = v;
    __syncthreads();
    float total = 0.0f;
    if (tid == 0) {
        #pragma unroll
        for (int w = 0; w < NWARPS; ++w) total += red[w];
    }
    return total;
}

// ---------------- kernel 1: Morlet bank, pre-permuted to 2D-bitrev ----------------
__global__ void k_psi() {
    int idx = blockIdx.x * blockDim.x + threadIdx.x;
    if (idx >= NJ * NL * PLANE) return;
    int p   = idx >> 14;
    int pos = idx & (PLANE - 1);
    int R = pos >> 7, C = pos & 127;
    int r = __brev((unsigned)R) >> 25;
    int c = __brev((unsigned)C) >> 25;
    int j = p >> 2, l = p & 3;
    float fr = (float)(r < 64 ? r : r - 128) * (6.283185307179586f / 128.0f);
    float fc = (float)(c < 64 ? c : c - 128) * (6.283185307179586f / 128.0f);
    float k0    = 2.356194490192345f / (float)(1 << j);
    float sigma = 0.8f * (float)(1 << j);
    float s2    = sigma * sigma;
    float theta = 0.7853981633974483f * (float)l;
    float k0x = k0 * cosf(theta), k0y = k0 * sinf(theta);
    float beta = expf(-0.5f * s2 * k0 * k0);
    float dx = fr - k0x, dy = fc - k0y;
    float g1 = expf(-0.5f * s2 * (dx*dx + dy*dy));
    float g0 = expf(-0.5f * s2 * (fr*fr + fc*fc));
    g_psi[idx] = g1 - beta * g0;
}

// ---------------- kernel 2: fft2(image) + s0 (fp32 shared, 1 CTA/SM, 64 blocks) ----------------
__global__ void __launch_bounds__(NTI, 1) k_img(const float* __restrict__ img) {
    extern __shared__ unsigned char smraw[];
    float2* S   = (float2*)smraw;
    float2* tw  = S + NN * STRIDE;
    float*  red = (float*)(tw + 128);
    int b = blockIdx.x, tid = threadIdx.x;
    int u = tid & 15, g = tid >> 4;
    init_tw(tw, tid);
    __syncthreads();
    const float* ip = img + (size_t)b * PLANE;
    float lsum = 0.0f;
    #pragma unroll
    for (int iter = 0; iter < 2; ++iter) {
        int r = g + 64 * iter;
        float2 x[8];
        #pragma unroll
        for (int i = 0; i < 8; ++i) {
            float v = ip[r * NN + u + 16*i];
            lsum += v;
            x[i] = make_float2(v, 0.0f);
        }
        fft128_fwd(x, u, tw);
        #pragma unroll
        for (int i = 0; i < 8; ++i) S[r * STRIDE + u + 16*i] = x[i];
    }
    float tot = block_sum<NTI/32>(lsum, red, tid);
    if (tid == 0) g_s0[b] = tot * (1.0f / 16384.0f);
    #pragma unroll
    for (int iter = 0; iter < 2; ++iter) {
        int c = g + 64 * iter;
        float2 x[8];
        #pragma unroll
        for (int i = 0; i < 8; ++i) x[i] = S[(u + 16*i) * STRIDE + c];
        fft128_fwd(x, u, tw);
        #pragma unroll
        for (int i = 0; i < 8; ++i) S[(u + 16*i) * STRIDE + c] = x[i];
    }
    __syncthreads();
    float2* op = g_ihat + (size_t)b * PLANE;
    for (int i = tid; i < PLANE; i += NTI)
        op[i] = S[(i >> 7) * STRIDE + (i & 127)];
}

// ---------------- kernel 3: order 1 (fp16 shared, 2 CTAs/SM) ----------------
__global__ void __launch_bounds__(NTS, 2) k_o1() {
    extern __shared__ unsigned char smraw[];
    __half2* S  = (__half2*)smraw;
    float2*  tw = (float2*)(smraw + SH_PLANE_BYTES);
    float*   red= (float*)(tw + 128);
    int tid = threadIdx.x;
    int u = tid & 15, hf = (tid >> 4) & 1, w = tid >> 5;
    int rw = (w + (w & 8)) + hf * 8;      // warp rows: r0 and r0+8 -> disjoint banks
    int cw = 2 * w + hf;                  // warp cols: 2w and 2w+1 -> even/odd banks
    int b  = blockIdx.x >> 4;
    int j1 = (blockIdx.x >> 2) & 3;
    int l1 = blockIdx.x & 3;
    init_tw(tw, tid);
    __syncthreads();
    const float2* ih = g_ihat + (size_t)b * PLANE;
    const float*  ps = g_psi + (size_t)(j1 * NL + l1) * PLANE;
    #pragma unroll
    for (int iter = 0; iter < 4; ++iter) {          // fused load*psi + inverse rows
        int r = rw + 32 * iter;
        float2 x[8];
        #pragma unroll
        for (int i = 0; i < 8; ++i) {
            int p = r * NN + u + 16*i;
            float2 v = ih[p];
            float  f = ps[p];
            x[i] = make_float2(v.x * f, v.y * f);
        }
        fft128_inv(x, u, tw);
        #pragma unroll
        for (int i = 0; i < 8; ++i) S[r * STRH + u + 16*i] = __float22half2_rn(x[i]);
    }
    __syncthreads();
    float lsum = 0.0f;
    #pragma unroll
    for (int iter = 0; iter < 4; ++iter) {          // inverse cols -> |.| -> forward cols
        int c = cw + 32 * iter;
        float2 x[8];
        #pragma unroll
        for (int i = 0; i < 8; ++i) x[i] = __half22float2(S[(u + 16*i) * STRH + c]);
        fft128_inv(x, u, tw);
        #pragma unroll
        for (int i = 0; i < 8; ++i) {
            float m = fast_mag(x[i]) * (1.0f / 16384.0f);
            lsum += m;
            x[i] = make_float2(m, 0.0f);
        }
        fft128_fwd(x, u, tw);
        #pragma unroll
        for (int i = 0; i < 8; ++i) S[(u + 16*i) * STRH + c] = __float22half2_rn(x[i]);
    }
    float tot = block_sum<NTS/32>(lsum, red, tid);  // sync inside orders S stores
    if (tid == 0) g_s1p[blockIdx.x] = tot;
    float2* op = g_u1hat + (size_t)blockIdx.x * PLANE;
    #pragma unroll
    for (int iter = 0; iter < 4; ++iter) {          // forward rows, write out from regs
        int r = rw + 32 * iter;
        float2 x[8];
        #pragma unroll
        for (int i = 0; i < 8; ++i) x[i] = __half22float2(S[r * STRH + u + 16*i]);
        fft128_fwd(x, u, tw);
        #pragma unroll
        for (int i = 0; i < 8; ++i) op[r * NN + u + 16*i] = x[i];
    }
}

// ---------------- kernel 4: order 2 (fp16 shared, 2 CTAs/SM) ----------------
__global__ void __launch_bounds__(NTS, 2) k_o2() {
    extern __shared__ unsigned char smraw[];
    __half2* S  = (__half2*)smraw;
    float2*  tw = (float2*)(smraw + SH_PLANE_BYTES);
    float*   red= (float*)(tw + 128);
    int tid = threadIdx.x;
    int u = tid & 15, hf = (tid >> 4) & 1, w = tid >> 5;
    int rw = (w + (w & 8)) + hf * 8;
    int cw = 2 * w + hf;
    int b    = blockIdx.x / 96;
    int rem  = blockIdx.x - b * 96;
    int pair = rem >> 4;
    int l1   = (rem >> 2) & 3;
    int l2   = rem & 3;
    int j1 = PJ1[pair], j2 = PJ2[pair];
    init_tw(tw, tid);
    __syncthreads();
    const float2* uh = g_u1hat + (size_t)(((b * NJ + j1) * NL) + l1) * PLANE;
    const float*  ps = g_psi + (size_t)(j2 * NL + l2) * PLANE;
    #pragma unroll
    for (int iter = 0; iter < 4; ++iter) {          // fused load*psi + inverse rows
        int r = rw + 32 * iter;
        float2 x[8];
        #pragma unroll
        for (int i = 0; i < 8; ++i) {
            int p = r * NN + u + 16*i;
            float2 v = uh[p];
            float  f = ps[p];
            x[i] = make_float2(v.x * f, v.y * f);
        }
        fft128_inv(x, u, tw);
        #pragma unroll
        for (int i = 0; i < 8; ++i) S[r * STRH + u + 16*i] = __float22half2_rn(x[i]);
    }
    __syncthreads();
    float lsum = 0.0f;
    #pragma unroll
    for (int iter = 0; iter < 4; ++iter) {          // inverse cols, |.| from regs
        int c = cw + 32 * iter;
        float2 x[8];
        #pragma unroll
        for (int i = 0; i < 8; ++i) x[i] = __half22float2(S[(u + 16*i) * STRH + c]);
        fft128_inv(x, u, tw);
        #pragma unroll
        for (int i = 0; i < 8; ++i)
            lsum += fast_mag(x[i]);
    }
    float tot = block_sum<NTS/32>(lsum, red, tid);
    if (tid == 0) g_s2p[blockIdx.x] = tot;
}

// ---------------- kernel 5: combine + MLP ----------------
__global__ void k_head(const float* __restrict__ fc1w, const float* __restrict__ fc1b,
                       const float* __restrict__ fc2w, const float* __restrict__ fc2b,
                       float* __restrict__ out) {
    int b = blockIdx.x;
    if (threadIdx.x != 0) return;
    float coeff[11];
    coeff[0] = g_s0[b];
    #pragma unroll
    for (int j = 0; j < 4; ++j) {
        float s = 0.0f;
        #pragma unroll
        for (int l = 0; l < 4; ++l) s += g_s1p[(b * 4 + j) * 4 + l];
        coeff[1 + j] = s * (1.0f / (4.0f * 16384.0f));
    }
    #pragma unroll
    for (int p = 0; p < 6; ++p) {
        float s = 0.0f;
        #pragma unroll
        for (int k = 0; k < 16; ++k) s += g_s2p[(b * 6 + p) * 16 + k];
        coeff[5 + p] = s * (1.0f / 16384.0f) * (1.0f / (16.0f * 16384.0f));
    }
    float h[4];
    #pragma unroll
    for (int k = 0; k < 4; ++k) {
        float a = fc1b[k];
        #pragma unroll
        for (int i = 0; i < 11; ++i) a += coeff[i] * fc1w[k * 11 + i];
        h[k] = fmaxf(a, 0.0f);
    }
    #pragma unroll
    for (int o = 0; o < 10; ++o) {
        float a = fc2b[o];
        #pragma unroll
        for (int k = 0; k < 4; ++k) a += h[k] * fc2w[o * 4 + k];
        out[b * 10 + o] = 1.0f / (1.0f + expf(-a));
    }
}

// ---------------- launch ----------------
extern "C" void kernel_launch(void* const* d_in, const int* in_sizes, int n_in,
                              void* d_out, int out_size) {
    (void)in_sizes; (void)n_in; (void)out_size;
    const float* img  = (const float*)d_in[0];
    const float* fc1w = (const float*)d_in[1];
    const float* fc1b = (const float*)d_in[2];
    const float* fc2w = (const float*)d_in[3];
    const float* fc2b = (const float*)d_in[4];
    float* out = (float*)d_out;

    const size_t SMEM_IMG = (size_t)(NN * STRIDE + 128) * sizeof(float2) + (NTI / 32) * sizeof(float);
    const size_t SMEM_O   = SH_PLANE_BYTES + 128 * sizeof(float2) + (NTS / 32) * sizeof(float);
    cudaFuncSetAttribute(k_img, cudaFuncAttributeMaxDynamicSharedMemorySize, (int)SMEM_IMG);
    cudaFuncSetAttribute(k_o1,  cudaFuncAttributeMaxDynamicSharedMemorySize, (int)SMEM_O);
    cudaFuncSetAttribute(k_o2,  cudaFuncAttributeMaxDynamicSharedMemorySize, (int)SMEM_O);

    k_psi<<<(NJ * NL * PLANE + 255) / 256, 256>>>();
    k_img<<<BATCH, NTI, SMEM_IMG>>>(img);
    k_o1 <<<BATCH * NJ * NL, NTS, SMEM_O>>>();
    k_o2 <<<BATCH * NPAIR * NL * NL, NTS, SMEM_O>>>();
    k_head<<<BATCH, 32>>>(fc1w, fc1b, fc2w, fc2b, out);
}